// round 1
// baseline (speedup 1.0000x reference)
#include <cuda_runtime.h>
#include <math.h>

// Problem constants
#define B_    4
#define L_    2048
#define D_    768
#define H_    12
#define DH_   64
#define F_    3072
#define KS_   307              // round(0.15 * 2048)
#define BL_   (B_*L_)          // 8192
#define MSEL_ (B_*KS_)         // 1228

// ---------------- scratch (static device globals; allocation-free) ----------
__device__ float g_normed[BL_*(size_t)D_];
__device__ float g_scores[BL_];
__device__ float g_ssum[B_];
__device__ int   g_selidx[MSEL_];
__device__ int   g_selpos[BL_];
__device__ float g_ppart[B_*16*D_];
__device__ float g_pooled[B_*D_];
__device__ float g_pooledWm[B_*D_];
__device__ float g_kf[BL_*(size_t)D_];
__device__ float g_vf[BL_*(size_t)D_];
__device__ float g_mixb[BL_*(size_t)D_];
__device__ float g_qsel[MSEL_*(size_t)D_];
__device__ float g_logits[(size_t)B_*H_*KS_*L_];   // 120.7 MB
__device__ float g_ctx[MSEL_*(size_t)D_];
__device__ float g_attno[MSEL_*(size_t)D_];
__device__ float g_h[BL_*(size_t)D_];
__device__ float g_n2[BL_*(size_t)D_];
__device__ float g_t[BL_*(size_t)F_];              // 100.7 MB

// ---------------- reductions ----------------
__device__ __forceinline__ float blockReduceSum(float v, float* sh) {
    __syncthreads();
    int lane = threadIdx.x & 31, w = threadIdx.x >> 5;
    #pragma unroll
    for (int o = 16; o > 0; o >>= 1) v += __shfl_xor_sync(0xffffffffu, v, o);
    if (lane == 0) sh[w] = v;
    __syncthreads();
    int nw = (blockDim.x + 31) >> 5;
    if (w == 0) {
        v = (lane < nw) ? sh[lane] : 0.f;
        #pragma unroll
        for (int o = 16; o > 0; o >>= 1) v += __shfl_xor_sync(0xffffffffu, v, o);
        if (lane == 0) sh[0] = v;
    }
    __syncthreads();
    return sh[0];
}

__device__ __forceinline__ float blockReduceMax(float v, float* sh) {
    __syncthreads();
    int lane = threadIdx.x & 31, w = threadIdx.x >> 5;
    #pragma unroll
    for (int o = 16; o > 0; o >>= 1) v = fmaxf(v, __shfl_xor_sync(0xffffffffu, v, o));
    if (lane == 0) sh[w] = v;
    __syncthreads();
    int nw = (blockDim.x + 31) >> 5;
    if (w == 0) {
        v = (lane < nw) ? sh[lane] : -1e30f;
        #pragma unroll
        for (int o = 16; o > 0; o >>= 1) v = fmaxf(v, __shfl_xor_sync(0xffffffffu, v, o));
        if (lane == 0) sh[0] = v;
    }
    __syncthreads();
    return sh[0];
}

// ---------------- K1: LN1 + router score ----------------
__global__ void ln1_router_kernel(const float* __restrict__ x, const float* __restrict__ g1,
                                  const float* __restrict__ b1, const float* __restrict__ Wr,
                                  const float* __restrict__ br) {
    int tok = blockIdx.x;
    int t = threadIdx.x;   // 256
    const float* xr = x + (size_t)tok * D_;
    __shared__ float sh[32];
    float v[3]; float s = 0.f, sq = 0.f;
    #pragma unroll
    for (int i = 0; i < 3; i++) { float u = xr[t + 256*i]; v[i] = u; s += u; sq += u*u; }
    s  = blockReduceSum(s,  sh);
    sq = blockReduceSum(sq, sh);
    float mean = s * (1.f/D_);
    float var  = sq * (1.f/D_) - mean*mean;
    float rstd = rsqrtf(var + 1e-5f);
    float dot = 0.f;
    #pragma unroll
    for (int i = 0; i < 3; i++) {
        int d = t + 256*i;
        float nv = (v[i] - mean) * rstd * g1[d] + b1[d];
        g_normed[(size_t)tok*D_ + d] = nv;
        dot += nv * Wr[d];
    }
    dot = blockReduceSum(dot, sh);
    if (t == 0) g_scores[tok] = 1.f / (1.f + expf(-(dot + br[0])));
}

// ---------------- K2: exact top-k (lowest scores) via bitonic sort ----------
__global__ void topk_kernel() {
    int b = blockIdx.x, t = threadIdx.x;   // 1024 threads
    __shared__ unsigned long long keys[L_];
    __shared__ float sh[32];
    float s0 = g_scores[b*L_ + t];
    float s1 = g_scores[b*L_ + t + 1024];
    // score > 0 (sigmoid) -> float bits are monotonic; idx in low bits = tie-break by index
    keys[t]        = ((unsigned long long)__float_as_uint(s0) << 32) | (unsigned)t;
    keys[t + 1024] = ((unsigned long long)__float_as_uint(s1) << 32) | (unsigned)(t + 1024);
    g_selpos[b*L_ + t] = -1;
    g_selpos[b*L_ + t + 1024] = -1;
    float tot = blockReduceSum(s0 + s1, sh);
    if (t == 0) g_ssum[b] = tot + 1e-6f;
    for (unsigned k = 2; k <= (unsigned)L_; k <<= 1) {
        for (unsigned j = k >> 1; j > 0; j >>= 1) {
            __syncthreads();
            for (unsigned i = t; i < (unsigned)L_; i += 1024) {
                unsigned ixj = i ^ j;
                if (ixj > i) {
                    unsigned long long a = keys[i], c = keys[ixj];
                    bool up = ((i & k) == 0);
                    if ((a > c) == up) { keys[i] = c; keys[ixj] = a; }
                }
            }
        }
    }
    __syncthreads();
    if (t < KS_) {
        int tok = (int)(unsigned)(keys[t] & 0xffffffffULL);
        g_selidx[b*KS_ + t] = b*L_ + tok;             // global row into g_normed
        g_selpos[b*L_ + tok] = b*KS_ + t;             // compact position
    }
}

// ---------------- K3: coherence-weighted pooling ----------------
__global__ void pooled_part_kernel() {
    int b = blockIdx.y, ch = blockIdx.x;   // 16 chunks
    int d = threadIdx.x;                   // 768
    float acc = 0.f;
    int l0 = ch * (L_/16);
    for (int l = l0; l < l0 + L_/16; l++)
        acc += g_scores[b*L_ + l] * g_normed[((size_t)(b*L_ + l))*D_ + d];
    g_ppart[(b*16 + ch)*D_ + d] = acc;
}
__global__ void pooled_fin_kernel() {
    int b = blockIdx.x; int d = threadIdx.x;  // 768
    float acc = 0.f;
    #pragma unroll
    for (int c = 0; c < 16; c++) acc += g_ppart[(b*16 + c)*D_ + d];
    g_pooled[b*D_ + d] = acc / g_ssum[b];
}
__global__ void pooledwm_kernel(const float* __restrict__ Wm) {
    int b = blockIdx.y;
    int n = blockIdx.x*256 + threadIdx.x;
    float acc = 0.f;
    for (int d = 0; d < D_; d++) acc += g_pooled[b*D_ + d] * Wm[d*D_ + n];
    g_pooledWm[b*D_ + n] = acc;
}

// ---------------- K4: tiled fp32 GEMM (128x128x8, 8x8/thread) ----------------
// C[M,N] = act( A[M,K] @ Bm[K,N] + bias[N] ) (+ Rm[M,N])
// If GATHER, A row index is gidx[m] (row stride K).
template<int ACT, bool GATHER, bool RESID>
__global__ void gemm128(const float* __restrict__ A, const int* __restrict__ gidx,
                        const float* __restrict__ Bm, const float* __restrict__ bias,
                        const float* __restrict__ Rm, float* __restrict__ C,
                        int M, int N, int K) {
    __shared__ float As[8][128];
    __shared__ float Bs[8][128];
    int tid = threadIdx.x;
    int m0 = blockIdx.y * 128, n0 = blockIdx.x * 128;
    int tx = tid & 15, ty = tid >> 4;

    int ai = tid >> 1;
    int ak = (tid & 1) * 4;
    int arow = m0 + ai;
    bool avalid = arow < M;
    int arowg = avalid ? (GATHER ? gidx[arow] : arow) : 0;

    int bk = tid >> 5;
    int bj = (tid & 31) * 4;

    float acc[8][8] = {};
    for (int k0 = 0; k0 < K; k0 += 8) {
        float4 av = avalid ? *(const float4*)&A[(size_t)arowg*K + k0 + ak]
                           : make_float4(0.f,0.f,0.f,0.f);
        As[ak+0][ai] = av.x; As[ak+1][ai] = av.y; As[ak+2][ai] = av.z; As[ak+3][ai] = av.w;
        *(float4*)&Bs[bk][bj] = *(const float4*)&Bm[(size_t)(k0+bk)*N + n0 + bj];
        __syncthreads();
        #pragma unroll
        for (int kk = 0; kk < 8; kk++) {
            float a[8], b[8];
            *(float4*)&a[0] = *(const float4*)&As[kk][ty*8];
            *(float4*)&a[4] = *(const float4*)&As[kk][ty*8+4];
            *(float4*)&b[0] = *(const float4*)&Bs[kk][tx*8];
            *(float4*)&b[4] = *(const float4*)&Bs[kk][tx*8+4];
            #pragma unroll
            for (int r = 0; r < 8; r++)
                #pragma unroll
                for (int c = 0; c < 8; c++)
                    acc[r][c] += a[r]*b[c];
        }
        __syncthreads();
    }
    #pragma unroll
    for (int r = 0; r < 8; r++) {
        int m = m0 + ty*8 + r;
        if (m < M) {
            size_t rowoff = (size_t)m * N;
            #pragma unroll
            for (int c = 0; c < 8; c++) {
                int n = n0 + tx*8 + c;
                float val = acc[r][c] + bias[n];
                if (ACT == 1) val = 0.5f * val * (1.f + erff(val * 0.70710678118654752f));
                if (RESID) val += Rm[rowoff + n];
                C[rowoff + n] = val;
            }
        }
    }
}

// ---------------- K5: logits = Qsel @ K^T / sqrt(dh) -------------------------
__global__ void logits_k() {
    int bh = blockIdx.z; int b = bh / H_, h = bh % H_;
    int i0 = blockIdx.y * 32, j0 = blockIdx.x * 128;
    int t = threadIdx.x;  // 256
    __shared__ float Qs[32][68];
    __shared__ float Ks[128][68];
    #pragma unroll
    for (int q = 0; q < 2; q++) {
        int fi = q*256 + t; int r = fi >> 4, c4 = fi & 15;
        int i = i0 + r;
        float4 val = make_float4(0.f,0.f,0.f,0.f);
        if (i < KS_) val = *(const float4*)&g_qsel[((size_t)(b*KS_ + i))*D_ + h*DH_ + c4*4];
        *(float4*)&Qs[r][c4*4] = val;
    }
    #pragma unroll
    for (int q = 0; q < 8; q++) {
        int fi = q*256 + t; int r = fi >> 4, c4 = fi & 15;
        *(float4*)&Ks[r][c4*4] =
            *(const float4*)&g_kf[((size_t)(b*L_ + j0 + r))*D_ + h*DH_ + c4*4];
    }
    __syncthreads();
    int ti = t >> 5, tj = t & 31;
    float acc[4][4] = {};
    #pragma unroll
    for (int d = 0; d < 64; d += 4) {
        float4 aq[4], bk4[4];
        #pragma unroll
        for (int r = 0; r < 4; r++) aq[r]  = *(const float4*)&Qs[ti*4 + r][d];
        #pragma unroll
        for (int c = 0; c < 4; c++) bk4[c] = *(const float4*)&Ks[tj + 32*c][d];
        #pragma unroll
        for (int r = 0; r < 4; r++)
            #pragma unroll
            for (int c = 0; c < 4; c++)
                acc[r][c] += aq[r].x*bk4[c].x + aq[r].y*bk4[c].y
                           + aq[r].z*bk4[c].z + aq[r].w*bk4[c].w;
    }
    const float scale = 0.125f;  // 1/sqrt(64)
    #pragma unroll
    for (int r = 0; r < 4; r++) {
        int i = i0 + ti*4 + r;
        if (i < KS_) {
            #pragma unroll
            for (int c = 0; c < 4; c++) {
                int j = j0 + tj + 32*c;
                g_logits[((size_t)bh*KS_ + i)*L_ + j] = acc[r][c] * scale;
            }
        }
    }
}

// ---------------- K6: softmax over keys ----------------
__global__ void softmax_kernel() {
    size_t row = blockIdx.x;
    float* p = g_logits + row * (size_t)L_;
    int t = threadIdx.x;   // 256
    __shared__ float sh[32];
    float v[8]; float mx = -1e30f;
    #pragma unroll
    for (int i = 0; i < 8; i++) { v[i] = p[t + 256*i]; mx = fmaxf(mx, v[i]); }
    mx = blockReduceMax(mx, sh);
    float s = 0.f;
    #pragma unroll
    for (int i = 0; i < 8; i++) { v[i] = expf(v[i] - mx); s += v[i]; }
    s = blockReduceSum(s, sh);
    float inv = 1.f / s;
    #pragma unroll
    for (int i = 0; i < 8; i++) p[t + 256*i] = v[i] * inv;
}

// ---------------- K7: ctx = probs @ V ----------------
__global__ void ctx_kernel() {
    int bh = blockIdx.y; int b = bh / H_, h = bh % H_;
    int i0 = blockIdx.x * 32;
    int t = threadIdx.x;   // 256
    __shared__ float Ps[32][68];
    __shared__ float Vs[64][68];
    int ti = t >> 5, tj = t & 31;
    float acc[4][2] = {};
    for (int l0 = 0; l0 < L_; l0 += 64) {
        #pragma unroll
        for (int q = 0; q < 2; q++) {
            int fi = q*256 + t; int r = fi >> 4, c4 = fi & 15;
            int i = i0 + r;
            float4 val = make_float4(0.f,0.f,0.f,0.f);
            if (i < KS_) val = *(const float4*)&g_logits[((size_t)bh*KS_ + i)*L_ + l0 + c4*4];
            *(float4*)&Ps[r][c4*4] = val;
        }
        #pragma unroll
        for (int q = 0; q < 4; q++) {
            int fi = q*256 + t; int r = fi >> 4, c4 = fi & 15;
            *(float4*)&Vs[r][c4*4] =
                *(const float4*)&g_vf[((size_t)(b*L_ + l0 + r))*D_ + h*DH_ + c4*4];
        }
        __syncthreads();
        #pragma unroll
        for (int kk = 0; kk < 64; kk += 4) {
            float4 ap[4];
            #pragma unroll
            for (int r = 0; r < 4; r++) ap[r] = *(const float4*)&Ps[ti*4 + r][kk];
            #pragma unroll
            for (int c = 0; c < 2; c++) {
                int n = tj + 32*c;
                float v0 = Vs[kk][n], v1 = Vs[kk+1][n], v2 = Vs[kk+2][n], v3 = Vs[kk+3][n];
                #pragma unroll
                for (int r = 0; r < 4; r++)
                    acc[r][c] += ap[r].x*v0 + ap[r].y*v1 + ap[r].z*v2 + ap[r].w*v3;
            }
        }
        __syncthreads();
    }
    #pragma unroll
    for (int r = 0; r < 4; r++) {
        int i = i0 + ti*4 + r;
        if (i < KS_) {
            #pragma unroll
            for (int c = 0; c < 2; c++)
                g_ctx[((size_t)(b*KS_ + i))*D_ + h*DH_ + tj + 32*c] = acc[r][c];
        }
    }
}

// ---------------- K9: merge paths + residual + LN2 ----------------
__global__ void merge_ln2_kernel(const float* __restrict__ x, const float* __restrict__ g2,
                                 const float* __restrict__ b2) {
    int tok = blockIdx.x;
    int b = tok >> 11;        // / L_
    int t = threadIdx.x;      // 256
    int pos = g_selpos[tok];
    float sc = g_scores[tok];
    __shared__ float sh[32];
    float hv[3]; float s = 0.f, sq = 0.f;
    #pragma unroll
    for (int i = 0; i < 3; i++) {
        int d = t + 256*i;
        float mg;
        if (pos >= 0) mg = g_attno[(size_t)pos*D_ + d];
        else          mg = g_mixb[(size_t)tok*D_ + d] + sc * g_pooledWm[b*D_ + d];
        float u = x[(size_t)tok*D_ + d] + mg;
        hv[i] = u;
        g_h[(size_t)tok*D_ + d] = u;
        s += u; sq += u*u;
    }
    s  = blockReduceSum(s,  sh);
    sq = blockReduceSum(sq, sh);
    float mean = s * (1.f/D_);
    float rstd = rsqrtf(sq*(1.f/D_) - mean*mean + 1e-5f);
    #pragma unroll
    for (int i = 0; i < 3; i++) {
        int d = t + 256*i;
        g_n2[(size_t)tok*D_ + d] = (hv[i] - mean) * rstd * g2[d] + b2[d];
    }
}

// ---------------- host launch ----------------
extern "C" void kernel_launch(void* const* d_in, const int* in_sizes, int n_in,
                              void* d_out, int out_size) {
    (void)in_sizes; (void)n_in; (void)out_size;
    const float* x   = (const float*)d_in[0];
    const float* g1  = (const float*)d_in[1];
    const float* b1  = (const float*)d_in[2];
    const float* g2  = (const float*)d_in[3];
    const float* b2  = (const float*)d_in[4];
    const float* Wr  = (const float*)d_in[5];
    const float* br  = (const float*)d_in[6];
    const float* Wq  = (const float*)d_in[7];
    const float* bq  = (const float*)d_in[8];
    const float* Wk  = (const float*)d_in[9];
    const float* bk  = (const float*)d_in[10];
    const float* Wv  = (const float*)d_in[11];
    const float* bv  = (const float*)d_in[12];
    const float* Wo  = (const float*)d_in[13];
    const float* bo  = (const float*)d_in[14];
    const float* Wm  = (const float*)d_in[15];
    const float* bm  = (const float*)d_in[16];
    const float* W1  = (const float*)d_in[17];
    const float* bf1 = (const float*)d_in[18];
    const float* W2  = (const float*)d_in[19];
    const float* bf2 = (const float*)d_in[20];
    float* out = (float*)d_out;

    float *p_normed, *p_kf, *p_vf, *p_mixb, *p_qsel, *p_ctx, *p_attno, *p_h, *p_n2, *p_t;
    int* p_selidx;
    cudaGetSymbolAddress((void**)&p_normed, g_normed);
    cudaGetSymbolAddress((void**)&p_kf,     g_kf);
    cudaGetSymbolAddress((void**)&p_vf,     g_vf);
    cudaGetSymbolAddress((void**)&p_mixb,   g_mixb);
    cudaGetSymbolAddress((void**)&p_qsel,   g_qsel);
    cudaGetSymbolAddress((void**)&p_ctx,    g_ctx);
    cudaGetSymbolAddress((void**)&p_attno,  g_attno);
    cudaGetSymbolAddress((void**)&p_h,      g_h);
    cudaGetSymbolAddress((void**)&p_n2,     g_n2);
    cudaGetSymbolAddress((void**)&p_t,      g_t);
    cudaGetSymbolAddress((void**)&p_selidx, g_selidx);

    // 1. LN1 + router scores
    ln1_router_kernel<<<BL_, 256>>>(x, g1, b1, Wr, br);
    // 2. top-k selection per batch (exact, index tie-break)
    topk_kernel<<<B_, 1024>>>();
    // 3. pooling + pooled@Wm
    pooled_part_kernel<<<dim3(16, B_), D_>>>();
    pooled_fin_kernel<<<B_, D_>>>();
    pooledwm_kernel<<<dim3(3, B_), 256>>>(Wm);
    // 4. dense projections: K, V, mixbase(+bm)
    gemm128<0,false,false><<<dim3(D_/128, BL_/128), 256>>>(p_normed, nullptr, Wk, bk, nullptr, p_kf,   BL_,  D_, D_);
    gemm128<0,false,false><<<dim3(D_/128, BL_/128), 256>>>(p_normed, nullptr, Wv, bv, nullptr, p_vf,   BL_,  D_, D_);
    gemm128<0,false,false><<<dim3(D_/128, BL_/128), 256>>>(p_normed, nullptr, Wm, bm, nullptr, p_mixb, BL_,  D_, D_);
    // 5. Q only for selected rows (gather)
    gemm128<0,true, false><<<dim3(D_/128, (MSEL_+127)/128), 256>>>(p_normed, p_selidx, Wq, bq, nullptr, p_qsel, MSEL_, D_, D_);
    // 6. attention on selected queries
    logits_k<<<dim3(L_/128, (KS_+31)/32, B_*H_), 256>>>();
    softmax_kernel<<<B_*H_*KS_, 256>>>();
    ctx_kernel<<<dim3((KS_+31)/32, B_*H_), 256>>>();
    gemm128<0,false,false><<<dim3(D_/128, (MSEL_+127)/128), 256>>>(p_ctx, nullptr, Wo, bo, nullptr, p_attno, MSEL_, D_, D_);
    // 7. merge + residual + LN2
    merge_ln2_kernel<<<BL_, 256>>>(x, g2, b2);
    // 8. FFN (exact GELU) + residual into output
    gemm128<1,false,false><<<dim3(F_/128, BL_/128), 256>>>(p_n2, nullptr, W1, bf1, nullptr, p_t, BL_, F_, D_);
    gemm128<0,false,true ><<<dim3(D_/128, BL_/128), 256>>>(p_t,  nullptr, W2, bf2, p_h,    out, BL_, D_, F_);
}

// round 2
// speedup vs baseline: 2.3090x; 2.3090x over previous
#include <cuda_runtime.h>
#include <math.h>
#include <stdint.h>

// Problem constants
#define B_    4
#define L_    2048
#define D_    768
#define H_    12
#define DH_   64
#define F_    3072
#define KS_   307              // round(0.15 * 2048)
#define BL_   (B_*L_)          // 8192
#define MSEL_ (B_*KS_)         // 1228

// ---------------- scratch (static device globals; allocation-free) ----------
__device__ float g_normed[BL_*(size_t)D_];
__device__ float g_scores[BL_];
__device__ float g_ssum[B_];
__device__ int   g_selidx[MSEL_];
__device__ int   g_selpos[BL_];
__device__ float g_ppart[B_*16*D_];
__device__ float g_pooled[B_*D_];
__device__ float g_pooledWm[B_*D_];
__device__ float g_kf[BL_*(size_t)D_];
__device__ float g_vf[BL_*(size_t)D_];
__device__ float g_mixb[BL_*(size_t)D_];
__device__ float g_qsel[MSEL_*(size_t)D_];
__device__ float g_logits[(size_t)B_*H_*KS_*L_];   // 120.7 MB
__device__ float g_ctx[MSEL_*(size_t)D_];
__device__ float g_attno[MSEL_*(size_t)D_];
__device__ float g_h[BL_*(size_t)D_];
__device__ float g_n2[BL_*(size_t)D_];
__device__ float g_t[BL_*(size_t)F_];              // 100.7 MB

// ---------------- reductions ----------------
__device__ __forceinline__ float blockReduceSum(float v, float* sh) {
    __syncthreads();
    int lane = threadIdx.x & 31, w = threadIdx.x >> 5;
    #pragma unroll
    for (int o = 16; o > 0; o >>= 1) v += __shfl_xor_sync(0xffffffffu, v, o);
    if (lane == 0) sh[w] = v;
    __syncthreads();
    int nw = (blockDim.x + 31) >> 5;
    if (w == 0) {
        v = (lane < nw) ? sh[lane] : 0.f;
        #pragma unroll
        for (int o = 16; o > 0; o >>= 1) v += __shfl_xor_sync(0xffffffffu, v, o);
        if (lane == 0) sh[0] = v;
    }
    __syncthreads();
    return sh[0];
}

__device__ __forceinline__ float blockReduceMax(float v, float* sh) {
    __syncthreads();
    int lane = threadIdx.x & 31, w = threadIdx.x >> 5;
    #pragma unroll
    for (int o = 16; o > 0; o >>= 1) v = fmaxf(v, __shfl_xor_sync(0xffffffffu, v, o));
    if (lane == 0) sh[w] = v;
    __syncthreads();
    int nw = (blockDim.x + 31) >> 5;
    if (w == 0) {
        v = (lane < nw) ? sh[lane] : -1e30f;
        #pragma unroll
        for (int o = 16; o > 0; o >>= 1) v = fmaxf(v, __shfl_xor_sync(0xffffffffu, v, o));
        if (lane == 0) sh[0] = v;
    }
    __syncthreads();
    return sh[0];
}

// ---------------- K1: LN1 + router score ----------------
__global__ void ln1_router_kernel(const float* __restrict__ x, const float* __restrict__ g1,
                                  const float* __restrict__ b1, const float* __restrict__ Wr,
                                  const float* __restrict__ br) {
    int tok = blockIdx.x;
    int t = threadIdx.x;   // 256
    const float* xr = x + (size_t)tok * D_;
    __shared__ float sh[32];
    float v[3]; float s = 0.f, sq = 0.f;
    #pragma unroll
    for (int i = 0; i < 3; i++) { float u = xr[t + 256*i]; v[i] = u; s += u; sq += u*u; }
    s  = blockReduceSum(s,  sh);
    sq = blockReduceSum(sq, sh);
    float mean = s * (1.f/D_);
    float var  = sq * (1.f/D_) - mean*mean;
    float rstd = rsqrtf(var + 1e-5f);
    float dot = 0.f;
    #pragma unroll
    for (int i = 0; i < 3; i++) {
        int d = t + 256*i;
        float nv = (v[i] - mean) * rstd * g1[d] + b1[d];
        g_normed[(size_t)tok*D_ + d] = nv;
        dot += nv * Wr[d];
    }
    dot = blockReduceSum(dot, sh);
    if (t == 0) g_scores[tok] = 1.f / (1.f + expf(-(dot + br[0])));
}

// ---------------- K2: exact top-k (lowest scores) via bitonic sort ----------
__global__ void topk_kernel() {
    int b = blockIdx.x, t = threadIdx.x;   // 1024 threads
    __shared__ unsigned long long keys[L_];
    __shared__ float sh[32];
    float s0 = g_scores[b*L_ + t];
    float s1 = g_scores[b*L_ + t + 1024];
    keys[t]        = ((unsigned long long)__float_as_uint(s0) << 32) | (unsigned)t;
    keys[t + 1024] = ((unsigned long long)__float_as_uint(s1) << 32) | (unsigned)(t + 1024);
    g_selpos[b*L_ + t] = -1;
    g_selpos[b*L_ + t + 1024] = -1;
    float tot = blockReduceSum(s0 + s1, sh);
    if (t == 0) g_ssum[b] = tot + 1e-6f;
    for (unsigned k = 2; k <= (unsigned)L_; k <<= 1) {
        for (unsigned j = k >> 1; j > 0; j >>= 1) {
            __syncthreads();
            for (unsigned i = t; i < (unsigned)L_; i += 1024) {
                unsigned ixj = i ^ j;
                if (ixj > i) {
                    unsigned long long a = keys[i], c = keys[ixj];
                    bool up = ((i & k) == 0);
                    if ((a > c) == up) { keys[i] = c; keys[ixj] = a; }
                }
            }
        }
    }
    __syncthreads();
    if (t < KS_) {
        int tok = (int)(unsigned)(keys[t] & 0xffffffffULL);
        g_selidx[b*KS_ + t] = b*L_ + tok;
        g_selpos[b*L_ + tok] = b*KS_ + t;
    }
}

// ---------------- K3: coherence-weighted pooling ----------------
__global__ void pooled_part_kernel() {
    int b = blockIdx.y, ch = blockIdx.x;
    int d = threadIdx.x;
    float acc = 0.f;
    int l0 = ch * (L_/16);
    for (int l = l0; l < l0 + L_/16; l++)
        acc += g_scores[b*L_ + l] * g_normed[((size_t)(b*L_ + l))*D_ + d];
    g_ppart[(b*16 + ch)*D_ + d] = acc;
}
__global__ void pooled_fin_kernel() {
    int b = blockIdx.x; int d = threadIdx.x;
    float acc = 0.f;
    #pragma unroll
    for (int c = 0; c < 16; c++) acc += g_ppart[(b*16 + c)*D_ + d];
    g_pooled[b*D_ + d] = acc / g_ssum[b];
}
__global__ void pooledwm_kernel(const float* __restrict__ Wm) {
    int b = blockIdx.y;
    int n = blockIdx.x*256 + threadIdx.x;
    float acc = 0.f;
    for (int d = 0; d < D_; d++) acc += g_pooled[b*D_ + d] * Wm[d*D_ + n];
    g_pooledWm[b*D_ + n] = acc;
}

// ---------------- tf32 helpers ----------------
__device__ __forceinline__ uint32_t f2tf32(float x) {
    uint32_t u;
    asm("cvt.rna.tf32.f32 %0, %1;" : "=r"(u) : "f"(x));
    return u;
}
__device__ __forceinline__ void mma16n8k8(float* c, const uint32_t* a, const uint32_t* b) {
    asm volatile(
        "mma.sync.aligned.m16n8k8.row.col.f32.tf32.tf32.f32 "
        "{%0,%1,%2,%3}, {%4,%5,%6,%7}, {%8,%9}, {%0,%1,%2,%3};"
        : "+f"(c[0]), "+f"(c[1]), "+f"(c[2]), "+f"(c[3])
        : "r"(a[0]), "r"(a[1]), "r"(a[2]), "r"(a[3]), "r"(b[0]), "r"(b[1]));
}

// ---------------- K4: tf32 tensor-core GEMM (128x128x16) --------------------
// C[M,N] = act( A[M,K] @ Bm[K,N] + bias[N] ) (+ Rm[M,N])
// Block: 256 thr = 8 warps (2 along M x 4 along N), warp tile 64x32.
// As/Bs stored k-major [16][132] (A transposed on smem store).
template<int ACT, bool GATHER, bool RESID>
__global__ __launch_bounds__(256)
void gemm_tf32(const float* __restrict__ A, const int* __restrict__ gidx,
               const float* __restrict__ Bm, const float* __restrict__ bias,
               const float* __restrict__ Rm, float* __restrict__ C,
               int M, int N, int K) {
    __shared__ float As[16][132];
    __shared__ float Bs[16][132];
    int tid = threadIdx.x;
    int wid = tid >> 5, lane = tid & 31;
    int wm = wid & 1, wn = wid >> 1;
    int g = lane >> 2, t = lane & 3;
    int m0 = blockIdx.y * 128, n0 = blockIdx.x * 128;

    // A loader: 512 float4/tile, 2 per thread (rows tid>>2 and 64+tid>>2)
    int amr0 = tid >> 2, amr1 = 64 + (tid >> 2);
    int akq = (tid & 3) * 4;
    int ar0 = m0 + amr0, ar1 = m0 + amr1;
    bool av0 = ar0 < M, av1 = ar1 < M;
    int ag0 = av0 ? (GATHER ? gidx[ar0] : ar0) : 0;
    int ag1 = av1 ? (GATHER ? gidx[ar1] : ar1) : 0;
    // B loader: 512 float4/tile, 2 per thread (k rows tid>>5 and 8+tid>>5)
    int bk0 = tid >> 5, bk1 = 8 + (tid >> 5);
    int bc = (tid & 31) * 4;

    float4 pa0, pa1, pb0, pb1;
    const float4 z4 = make_float4(0.f, 0.f, 0.f, 0.f);

    // prefetch tile 0
    pa0 = av0 ? *(const float4*)&A[(size_t)ag0*K + akq] : z4;
    pa1 = av1 ? *(const float4*)&A[(size_t)ag1*K + akq] : z4;
    pb0 = *(const float4*)&Bm[(size_t)bk0*N + n0 + bc];
    pb1 = *(const float4*)&Bm[(size_t)bk1*N + n0 + bc];
    // store tile 0 (tf32-rounded)
    As[akq+0][amr0] = __uint_as_float(f2tf32(pa0.x));
    As[akq+1][amr0] = __uint_as_float(f2tf32(pa0.y));
    As[akq+2][amr0] = __uint_as_float(f2tf32(pa0.z));
    As[akq+3][amr0] = __uint_as_float(f2tf32(pa0.w));
    As[akq+0][amr1] = __uint_as_float(f2tf32(pa1.x));
    As[akq+1][amr1] = __uint_as_float(f2tf32(pa1.y));
    As[akq+2][amr1] = __uint_as_float(f2tf32(pa1.z));
    As[akq+3][amr1] = __uint_as_float(f2tf32(pa1.w));
    {
        float4 q0, q1;
        q0.x = __uint_as_float(f2tf32(pb0.x)); q0.y = __uint_as_float(f2tf32(pb0.y));
        q0.z = __uint_as_float(f2tf32(pb0.z)); q0.w = __uint_as_float(f2tf32(pb0.w));
        q1.x = __uint_as_float(f2tf32(pb1.x)); q1.y = __uint_as_float(f2tf32(pb1.y));
        q1.z = __uint_as_float(f2tf32(pb1.z)); q1.w = __uint_as_float(f2tf32(pb1.w));
        *(float4*)&Bs[bk0][bc] = q0;
        *(float4*)&Bs[bk1][bc] = q1;
    }
    __syncthreads();

    float acc[4][4][4] = {};
    int mbase = wm * 64, nbase = wn * 32;

    for (int k0 = 0; k0 < K; k0 += 16) {
        bool more = (k0 + 16) < K;
        if (more) {
            int kn = k0 + 16;
            pa0 = av0 ? *(const float4*)&A[(size_t)ag0*K + kn + akq] : z4;
            pa1 = av1 ? *(const float4*)&A[(size_t)ag1*K + kn + akq] : z4;
            pb0 = *(const float4*)&Bm[(size_t)(kn + bk0)*N + n0 + bc];
            pb1 = *(const float4*)&Bm[(size_t)(kn + bk1)*N + n0 + bc];
        }
        #pragma unroll
        for (int kk = 0; kk < 16; kk += 8) {
            uint32_t af[4][4], bf[4][2];
            #pragma unroll
            for (int mt = 0; mt < 4; mt++) {
                int mb = mbase + mt*16 + g;
                af[mt][0] = __float_as_uint(As[kk + t][mb]);
                af[mt][1] = __float_as_uint(As[kk + t][mb + 8]);
                af[mt][2] = __float_as_uint(As[kk + t + 4][mb]);
                af[mt][3] = __float_as_uint(As[kk + t + 4][mb + 8]);
            }
            #pragma unroll
            for (int nt = 0; nt < 4; nt++) {
                int nb = nbase + nt*8 + g;
                bf[nt][0] = __float_as_uint(Bs[kk + t][nb]);
                bf[nt][1] = __float_as_uint(Bs[kk + t + 4][nb]);
            }
            #pragma unroll
            for (int mt = 0; mt < 4; mt++)
                #pragma unroll
                for (int nt = 0; nt < 4; nt++)
                    mma16n8k8(acc[mt][nt], af[mt], bf[nt]);
        }
        __syncthreads();
        if (more) {
            As[akq+0][amr0] = __uint_as_float(f2tf32(pa0.x));
            As[akq+1][amr0] = __uint_as_float(f2tf32(pa0.y));
            As[akq+2][amr0] = __uint_as_float(f2tf32(pa0.z));
            As[akq+3][amr0] = __uint_as_float(f2tf32(pa0.w));
            As[akq+0][amr1] = __uint_as_float(f2tf32(pa1.x));
            As[akq+1][amr1] = __uint_as_float(f2tf32(pa1.y));
            As[akq+2][amr1] = __uint_as_float(f2tf32(pa1.z));
            As[akq+3][amr1] = __uint_as_float(f2tf32(pa1.w));
            float4 q0, q1;
            q0.x = __uint_as_float(f2tf32(pb0.x)); q0.y = __uint_as_float(f2tf32(pb0.y));
            q0.z = __uint_as_float(f2tf32(pb0.z)); q0.w = __uint_as_float(f2tf32(pb0.w));
            q1.x = __uint_as_float(f2tf32(pb1.x)); q1.y = __uint_as_float(f2tf32(pb1.y));
            q1.z = __uint_as_float(f2tf32(pb1.z)); q1.w = __uint_as_float(f2tf32(pb1.w));
            *(float4*)&Bs[bk0][bc] = q0;
            *(float4*)&Bs[bk1][bc] = q1;
            __syncthreads();
        }
    }

    // epilogue
    #pragma unroll
    for (int mt = 0; mt < 4; mt++) {
        #pragma unroll
        for (int nt = 0; nt < 4; nt++) {
            int n = n0 + nbase + nt*8 + t*2;
            float bi0 = bias[n], bi1 = bias[n + 1];
            #pragma unroll
            for (int half = 0; half < 2; half++) {
                int m = m0 + mbase + mt*16 + g + half*8;
                if (m < M) {
                    float v0 = acc[mt][nt][half*2 + 0] + bi0;
                    float v1 = acc[mt][nt][half*2 + 1] + bi1;
                    if (ACT == 1) {
                        v0 = 0.5f * v0 * (1.f + erff(v0 * 0.70710678118654752f));
                        v1 = 0.5f * v1 * (1.f + erff(v1 * 0.70710678118654752f));
                    }
                    size_t off = (size_t)m * N + n;
                    if (RESID) { v0 += Rm[off]; v1 += Rm[off + 1]; }
                    float2 o; o.x = v0; o.y = v1;
                    *(float2*)&C[off] = o;
                }
            }
        }
    }
}

// ---------------- K5: logits = Qsel @ K^T / sqrt(dh) -------------------------
__global__ void logits_k() {
    int bh = blockIdx.z; int b = bh / H_, h = bh % H_;
    int i0 = blockIdx.y * 32, j0 = blockIdx.x * 128;
    int t = threadIdx.x;  // 256
    __shared__ float Qs[32][68];
    __shared__ float Ks[128][68];
    #pragma unroll
    for (int q = 0; q < 2; q++) {
        int fi = q*256 + t; int r = fi >> 4, c4 = fi & 15;
        int i = i0 + r;
        float4 val = make_float4(0.f,0.f,0.f,0.f);
        if (i < KS_) val = *(const float4*)&g_qsel[((size_t)(b*KS_ + i))*D_ + h*DH_ + c4*4];
        *(float4*)&Qs[r][c4*4] = val;
    }
    #pragma unroll
    for (int q = 0; q < 8; q++) {
        int fi = q*256 + t; int r = fi >> 4, c4 = fi & 15;
        *(float4*)&Ks[r][c4*4] =
            *(const float4*)&g_kf[((size_t)(b*L_ + j0 + r))*D_ + h*DH_ + c4*4];
    }
    __syncthreads();
    int ti = t >> 5, tj = t & 31;
    float acc[4][4] = {};
    #pragma unroll
    for (int d = 0; d < 64; d += 4) {
        float4 aq[4], bk4[4];
        #pragma unroll
        for (int r = 0; r < 4; r++) aq[r]  = *(const float4*)&Qs[ti*4 + r][d];
        #pragma unroll
        for (int c = 0; c < 4; c++) bk4[c] = *(const float4*)&Ks[tj + 32*c][d];
        #pragma unroll
        for (int r = 0; r < 4; r++)
            #pragma unroll
            for (int c = 0; c < 4; c++)
                acc[r][c] += aq[r].x*bk4[c].x + aq[r].y*bk4[c].y
                           + aq[r].z*bk4[c].z + aq[r].w*bk4[c].w;
    }
    const float scale = 0.125f;
    #pragma unroll
    for (int r = 0; r < 4; r++) {
        int i = i0 + ti*4 + r;
        if (i < KS_) {
            #pragma unroll
            for (int c = 0; c < 4; c++) {
                int j = j0 + tj + 32*c;
                g_logits[((size_t)bh*KS_ + i)*L_ + j] = acc[r][c] * scale;
            }
        }
    }
}

// ---------------- K6: softmax over keys ----------------
__global__ void softmax_kernel() {
    size_t row = blockIdx.x;
    float* p = g_logits + row * (size_t)L_;
    int t = threadIdx.x;   // 256
    __shared__ float sh[32];
    float v[8]; float mx = -1e30f;
    #pragma unroll
    for (int i = 0; i < 8; i++) { v[i] = p[t + 256*i]; mx = fmaxf(mx, v[i]); }
    mx = blockReduceMax(mx, sh);
    float s = 0.f;
    #pragma unroll
    for (int i = 0; i < 8; i++) { v[i] = expf(v[i] - mx); s += v[i]; }
    s = blockReduceSum(s, sh);
    float inv = 1.f / s;
    #pragma unroll
    for (int i = 0; i < 8; i++) p[t + 256*i] = v[i] * inv;
}

// ---------------- K7: ctx = probs @ V ----------------
__global__ void ctx_kernel() {
    int bh = blockIdx.y; int b = bh / H_, h = bh % H_;
    int i0 = blockIdx.x * 32;
    int t = threadIdx.x;   // 256
    __shared__ float Ps[32][68];
    __shared__ float Vs[64][68];
    int ti = t >> 5, tj = t & 31;
    float acc[4][2] = {};
    for (int l0 = 0; l0 < L_; l0 += 64) {
        #pragma unroll
        for (int q = 0; q < 2; q++) {
            int fi = q*256 + t; int r = fi >> 4, c4 = fi & 15;
            int i = i0 + r;
            float4 val = make_float4(0.f,0.f,0.f,0.f);
            if (i < KS_) val = *(const float4*)&g_logits[((size_t)bh*KS_ + i)*L_ + l0 + c4*4];
            *(float4*)&Ps[r][c4*4] = val;
        }
        #pragma unroll
        for (int q = 0; q < 4; q++) {
            int fi = q*256 + t; int r = fi >> 4, c4 = fi & 15;
            *(float4*)&Vs[r][c4*4] =
                *(const float4*)&g_vf[((size_t)(b*L_ + l0 + r))*D_ + h*DH_ + c4*4];
        }
        __syncthreads();
        #pragma unroll
        for (int kk = 0; kk < 64; kk += 4) {
            float4 ap[4];
            #pragma unroll
            for (int r = 0; r < 4; r++) ap[r] = *(const float4*)&Ps[ti*4 + r][kk];
            #pragma unroll
            for (int c = 0; c < 2; c++) {
                int n = tj + 32*c;
                float v0 = Vs[kk][n], v1 = Vs[kk+1][n], v2 = Vs[kk+2][n], v3 = Vs[kk+3][n];
                #pragma unroll
                for (int r = 0; r < 4; r++)
                    acc[r][c] += ap[r].x*v0 + ap[r].y*v1 + ap[r].z*v2 + ap[r].w*v3;
            }
        }
        __syncthreads();
    }
    #pragma unroll
    for (int r = 0; r < 4; r++) {
        int i = i0 + ti*4 + r;
        if (i < KS_) {
            #pragma unroll
            for (int c = 0; c < 2; c++)
                g_ctx[((size_t)(b*KS_ + i))*D_ + h*DH_ + tj + 32*c] = acc[r][c];
        }
    }
}

// ---------------- K9: merge paths + residual + LN2 ----------------
__global__ void merge_ln2_kernel(const float* __restrict__ x, const float* __restrict__ g2,
                                 const float* __restrict__ b2) {
    int tok = blockIdx.x;
    int b = tok >> 11;
    int t = threadIdx.x;
    int pos = g_selpos[tok];
    float sc = g_scores[tok];
    __shared__ float sh[32];
    float hv[3]; float s = 0.f, sq = 0.f;
    #pragma unroll
    for (int i = 0; i < 3; i++) {
        int d = t + 256*i;
        float mg;
        if (pos >= 0) mg = g_attno[(size_t)pos*D_ + d];
        else          mg = g_mixb[(size_t)tok*D_ + d] + sc * g_pooledWm[b*D_ + d];
        float u = x[(size_t)tok*D_ + d] + mg;
        hv[i] = u;
        g_h[(size_t)tok*D_ + d] = u;
        s += u; sq += u*u;
    }
    s  = blockReduceSum(s,  sh);
    sq = blockReduceSum(sq, sh);
    float mean = s * (1.f/D_);
    float rstd = rsqrtf(sq*(1.f/D_) - mean*mean + 1e-5f);
    #pragma unroll
    for (int i = 0; i < 3; i++) {
        int d = t + 256*i;
        g_n2[(size_t)tok*D_ + d] = (hv[i] - mean) * rstd * g2[d] + b2[d];
    }
}

// ---------------- host launch ----------------
extern "C" void kernel_launch(void* const* d_in, const int* in_sizes, int n_in,
                              void* d_out, int out_size) {
    (void)in_sizes; (void)n_in; (void)out_size;
    const float* x   = (const float*)d_in[0];
    const float* g1  = (const float*)d_in[1];
    const float* b1  = (const float*)d_in[2];
    const float* g2  = (const float*)d_in[3];
    const float* b2  = (const float*)d_in[4];
    const float* Wr  = (const float*)d_in[5];
    const float* br  = (const float*)d_in[6];
    const float* Wq  = (const float*)d_in[7];
    const float* bq  = (const float*)d_in[8];
    const float* Wk  = (const float*)d_in[9];
    const float* bk  = (const float*)d_in[10];
    const float* Wv  = (const float*)d_in[11];
    const float* bv  = (const float*)d_in[12];
    const float* Wo  = (const float*)d_in[13];
    const float* bo  = (const float*)d_in[14];
    const float* Wm  = (const float*)d_in[15];
    const float* bm  = (const float*)d_in[16];
    const float* W1  = (const float*)d_in[17];
    const float* bf1 = (const float*)d_in[18];
    const float* W2  = (const float*)d_in[19];
    const float* bf2 = (const float*)d_in[20];
    float* out = (float*)d_out;

    float *p_normed, *p_kf, *p_vf, *p_mixb, *p_qsel, *p_ctx, *p_attno, *p_h, *p_n2, *p_t;
    int* p_selidx;
    cudaGetSymbolAddress((void**)&p_normed, g_normed);
    cudaGetSymbolAddress((void**)&p_kf,     g_kf);
    cudaGetSymbolAddress((void**)&p_vf,     g_vf);
    cudaGetSymbolAddress((void**)&p_mixb,   g_mixb);
    cudaGetSymbolAddress((void**)&p_qsel,   g_qsel);
    cudaGetSymbolAddress((void**)&p_ctx,    g_ctx);
    cudaGetSymbolAddress((void**)&p_attno,  g_attno);
    cudaGetSymbolAddress((void**)&p_h,      g_h);
    cudaGetSymbolAddress((void**)&p_n2,     g_n2);
    cudaGetSymbolAddress((void**)&p_t,      g_t);
    cudaGetSymbolAddress((void**)&p_selidx, g_selidx);

    // 1. LN1 + router scores
    ln1_router_kernel<<<BL_, 256>>>(x, g1, b1, Wr, br);
    // 2. top-k selection per batch
    topk_kernel<<<B_, 1024>>>();
    // 3. pooling + pooled@Wm
    pooled_part_kernel<<<dim3(16, B_), D_>>>();
    pooled_fin_kernel<<<B_, D_>>>();
    pooledwm_kernel<<<dim3(3, B_), 256>>>(Wm);
    // 4. dense projections: K, V, mixbase(+bm)  [tf32 tensor cores]
    gemm_tf32<0,false,false><<<dim3(D_/128, BL_/128), 256>>>(p_normed, nullptr, Wk, bk, nullptr, p_kf,   BL_,  D_, D_);
    gemm_tf32<0,false,false><<<dim3(D_/128, BL_/128), 256>>>(p_normed, nullptr, Wv, bv, nullptr, p_vf,   BL_,  D_, D_);
    gemm_tf32<0,false,false><<<dim3(D_/128, BL_/128), 256>>>(p_normed, nullptr, Wm, bm, nullptr, p_mixb, BL_,  D_, D_);
    // 5. Q only for selected rows (gather)
    gemm_tf32<0,true, false><<<dim3(D_/128, (MSEL_+127)/128), 256>>>(p_normed, p_selidx, Wq, bq, nullptr, p_qsel, MSEL_, D_, D_);
    // 6. attention on selected queries
    logits_k<<<dim3(L_/128, (KS_+31)/32, B_*H_), 256>>>();
    softmax_kernel<<<B_*H_*KS_, 256>>>();
    ctx_kernel<<<dim3((KS_+31)/32, B_*H_), 256>>>();
    gemm_tf32<0,false,false><<<dim3(D_/128, (MSEL_+127)/128), 256>>>(p_ctx, nullptr, Wo, bo, nullptr, p_attno, MSEL_, D_, D_);
    // 7. merge + residual + LN2
    merge_ln2_kernel<<<BL_, 256>>>(x, g2, b2);
    // 8. FFN (exact GELU) + residual into output
    gemm_tf32<1,false,false><<<dim3(F_/128, BL_/128), 256>>>(p_n2, nullptr, W1, bf1, nullptr, p_t, BL_, F_, D_);
    gemm_tf32<0,false,true ><<<dim3(D_/128, BL_/128), 256>>>(p_t,  nullptr, W2, bf2, p_h,    out, BL_, D_, F_);
}

// round 4
// speedup vs baseline: 2.9783x; 1.2899x over previous
#include <cuda_runtime.h>
#include <math.h>
#include <stdint.h>

// Problem constants
#define B_    4
#define L_    2048
#define D_    768
#define H_    12
#define DH_   64
#define F_    3072
#define KS_   307              // round(0.15 * 2048)
#define BL_   (B_*L_)          // 8192
#define MSEL_ (B_*KS_)         // 1228

#define WSZ_  589824           // 768*768
#define W1SZ_ 2359296          // 768*3072

// ---------------- scratch (static device globals; allocation-free) ----------
__device__ float g_normed [BL_*(size_t)D_];   // exact fp32 (router/pool path)
__device__ float g_normedr[BL_*(size_t)D_];   // tf32-rounded (GEMM A path)
__device__ float g_scores[BL_];
__device__ float g_ssum[B_];
__device__ int   g_selidx[MSEL_];
__device__ int   g_selpos[BL_];
__device__ float g_ppart[B_*16*D_];
__device__ float g_pooled[B_*D_];
__device__ float g_pooledWm[B_*D_];
__device__ float g_kf[BL_*(size_t)D_];
__device__ float g_vf[BL_*(size_t)D_];
__device__ float g_mixb[BL_*(size_t)D_];
__device__ float g_qsel[MSEL_*(size_t)D_];
__device__ float g_logits[(size_t)B_*H_*KS_*L_];
__device__ float g_ctx[MSEL_*(size_t)D_];
__device__ float g_attno[MSEL_*(size_t)D_];
__device__ float g_h[BL_*(size_t)D_];
__device__ float g_n2[BL_*(size_t)D_];
__device__ float g_t[BL_*(size_t)F_];
__device__ float g_wbuf[5*(size_t)WSZ_ + 2*(size_t)W1SZ_];  // rounded weights

// ---------------- small helpers ----------------
__device__ __forceinline__ uint32_t smem_u32(const void* p) {
    uint32_t a;
    asm("{ .reg .u64 t; cvta.to.shared.u64 t, %1; cvt.u32.u64 %0, t; }"
        : "=r"(a) : "l"(p));
    return a;
}
__device__ __forceinline__ uint32_t f2tf32(float x) {
    uint32_t u;
    asm("cvt.rna.tf32.f32 %0, %1;" : "=r"(u) : "f"(x));
    return u;
}
__device__ __forceinline__ float tf32r(float x) { return __uint_as_float(f2tf32(x)); }
__device__ __forceinline__ void mma16n8k8(float* c, const uint32_t* a, const uint32_t* b) {
    asm volatile(
        "mma.sync.aligned.m16n8k8.row.col.f32.tf32.tf32.f32 "
        "{%0,%1,%2,%3}, {%4,%5,%6,%7}, {%8,%9}, {%0,%1,%2,%3};"
        : "+f"(c[0]), "+f"(c[1]), "+f"(c[2]), "+f"(c[3])
        : "r"(a[0]), "r"(a[1]), "r"(a[2]), "r"(a[3]), "r"(b[0]), "r"(b[1]));
}
__device__ __forceinline__ void ldsm4(uint32_t* r, uint32_t addr) {
    asm volatile("ldmatrix.sync.aligned.m8n8.x4.shared.b16 {%0,%1,%2,%3}, [%4];"
        : "=r"(r[0]), "=r"(r[1]), "=r"(r[2]), "=r"(r[3]) : "r"(addr));
}
__device__ __forceinline__ void cpasync16(uint32_t dst, const void* src, unsigned sz) {
    asm volatile("cp.async.cg.shared.global [%0], [%1], 16, %2;"
        :: "r"(dst), "l"(src), "r"(sz));
}
__device__ __forceinline__ void cpcommit() { asm volatile("cp.async.commit_group;"); }
__device__ __forceinline__ void cpwait0()  { asm volatile("cp.async.wait_group 0;"); }

// ---------------- reductions ----------------
__device__ __forceinline__ float blockReduceSum(float v, float* sh) {
    __syncthreads();
    int lane = threadIdx.x & 31, w = threadIdx.x >> 5;
    #pragma unroll
    for (int o = 16; o > 0; o >>= 1) v += __shfl_xor_sync(0xffffffffu, v, o);
    if (lane == 0) sh[w] = v;
    __syncthreads();
    int nw = (blockDim.x + 31) >> 5;
    if (w == 0) {
        v = (lane < nw) ? sh[lane] : 0.f;
        #pragma unroll
        for (int o = 16; o > 0; o >>= 1) v += __shfl_xor_sync(0xffffffffu, v, o);
        if (lane == 0) sh[0] = v;
    }
    __syncthreads();
    return sh[0];
}
__device__ __forceinline__ float blockReduceMax(float v, float* sh) {
    __syncthreads();
    int lane = threadIdx.x & 31, w = threadIdx.x >> 5;
    #pragma unroll
    for (int o = 16; o > 0; o >>= 1) v = fmaxf(v, __shfl_xor_sync(0xffffffffu, v, o));
    if (lane == 0) sh[w] = v;
    __syncthreads();
    int nw = (blockDim.x + 31) >> 5;
    if (w == 0) {
        v = (lane < nw) ? sh[lane] : -1e30f;
        #pragma unroll
        for (int o = 16; o > 0; o >>= 1) v = fmaxf(v, __shfl_xor_sync(0xffffffffu, v, o));
        if (lane == 0) sh[0] = v;
    }
    __syncthreads();
    return sh[0];
}

// ---------------- W prep: round weights to tf32 ----------------
__global__ void round_w_kernel(const float* __restrict__ in, float* __restrict__ out, int n4) {
    int i = blockIdx.x * blockDim.x + threadIdx.x;
    int stride = gridDim.x * blockDim.x;
    for (; i < n4; i += stride) {
        float4 v = ((const float4*)in)[i];
        v.x = tf32r(v.x); v.y = tf32r(v.y); v.z = tf32r(v.z); v.w = tf32r(v.w);
        ((float4*)out)[i] = v;
    }
}

// ---------------- K1: LN1 + router score ----------------
__global__ void ln1_router_kernel(const float* __restrict__ x, const float* __restrict__ g1,
                                  const float* __restrict__ b1, const float* __restrict__ Wr,
                                  const float* __restrict__ br) {
    int tok = blockIdx.x;
    int t = threadIdx.x;   // 256
    const float* xr = x + (size_t)tok * D_;
    __shared__ float sh[32];
    float v[3]; float s = 0.f, sq = 0.f;
    #pragma unroll
    for (int i = 0; i < 3; i++) { float u = xr[t + 256*i]; v[i] = u; s += u; sq += u*u; }
    s  = blockReduceSum(s,  sh);
    sq = blockReduceSum(sq, sh);
    float mean = s * (1.f/D_);
    float var  = sq * (1.f/D_) - mean*mean;
    float rstd = rsqrtf(var + 1e-5f);
    float dot = 0.f;
    #pragma unroll
    for (int i = 0; i < 3; i++) {
        int d = t + 256*i;
        float nv = (v[i] - mean) * rstd * g1[d] + b1[d];
        g_normed [(size_t)tok*D_ + d] = nv;
        g_normedr[(size_t)tok*D_ + d] = tf32r(nv);
        dot += nv * Wr[d];
    }
    dot = blockReduceSum(dot, sh);
    if (t == 0) g_scores[tok] = 1.f / (1.f + expf(-(dot + br[0])));
}

// ---------------- K2: exact top-k via bitonic sort ----------
__global__ void topk_kernel() {
    int b = blockIdx.x, t = threadIdx.x;   // 1024 threads
    __shared__ unsigned long long keys[L_];
    __shared__ float sh[32];
    float s0 = g_scores[b*L_ + t];
    float s1 = g_scores[b*L_ + t + 1024];
    keys[t]        = ((unsigned long long)__float_as_uint(s0) << 32) | (unsigned)t;
    keys[t + 1024] = ((unsigned long long)__float_as_uint(s1) << 32) | (unsigned)(t + 1024);
    g_selpos[b*L_ + t] = -1;
    g_selpos[b*L_ + t + 1024] = -1;
    float tot = blockReduceSum(s0 + s1, sh);
    if (t == 0) g_ssum[b] = tot + 1e-6f;
    for (unsigned k = 2; k <= (unsigned)L_; k <<= 1) {
        for (unsigned j = k >> 1; j > 0; j >>= 1) {
            __syncthreads();
            for (unsigned i = t; i < (unsigned)L_; i += 1024) {
                unsigned ixj = i ^ j;
                if (ixj > i) {
                    unsigned long long a = keys[i], c = keys[ixj];
                    bool up = ((i & k) == 0);
                    if ((a > c) == up) { keys[i] = c; keys[ixj] = a; }
                }
            }
        }
    }
    __syncthreads();
    if (t < KS_) {
        int tok = (int)(unsigned)(keys[t] & 0xffffffffULL);
        g_selidx[b*KS_ + t] = b*L_ + tok;
        g_selpos[b*L_ + tok] = b*KS_ + t;
    }
}

// ---------------- K3: coherence-weighted pooling ----------------
__global__ void pooled_part_kernel() {
    int b = blockIdx.y, ch = blockIdx.x;
    int d = threadIdx.x;
    float acc = 0.f;
    int l0 = ch * (L_/16);
    for (int l = l0; l < l0 + L_/16; l++)
        acc += g_scores[b*L_ + l] * g_normed[((size_t)(b*L_ + l))*D_ + d];
    g_ppart[(b*16 + ch)*D_ + d] = acc;
}
__global__ void pooled_fin_kernel() {
    int b = blockIdx.x; int d = threadIdx.x;
    float acc = 0.f;
    #pragma unroll
    for (int c = 0; c < 16; c++) acc += g_ppart[(b*16 + c)*D_ + d];
    g_pooled[b*D_ + d] = acc / g_ssum[b];
}
__global__ void pooledwm_kernel(const float* __restrict__ Wm) {
    int b = blockIdx.y;
    int n = blockIdx.x*256 + threadIdx.x;
    float acc = 0.f;
    for (int d = 0; d < D_; d++) acc += g_pooled[b*D_ + d] * Wm[d*D_ + n];
    g_pooledWm[b*D_ + n] = acc;
}

// ---------------- GEMM v3: tf32 mma + ldmatrix + cp.async ------------------
// C[M,N] = act( A[M,K] @ Bm[K,N] + bias[N] ) (+ Rm[M,N])
// 128 threads = 4 warps (2M x 2N), warp tile 64x64, block 128x128, k-tile 16.
// A and Bm MUST be pre-rounded to tf32 values.
#define ABYTES_ (128*20*4)
#define BBYTES_ (16*136*4)
template<int ACT, bool GATHER, bool RESID, bool ROUND_OUT>
__global__ __launch_bounds__(128)
void gemm_tc(const float* __restrict__ A, const int* __restrict__ gidx,
             const float* __restrict__ Bm, const float* __restrict__ bias,
             const float* __restrict__ Rm, float* __restrict__ C,
             int M, int N, int K) {
    __shared__ __align__(128) float As[2][128][20];   // m-major, pad to 20
    __shared__ __align__(128) float Bs[2][16][136];   // k-major, pad to 136
    const int tid = threadIdx.x, lane = tid & 31, wid = tid >> 5;
    const int wm = wid & 1, wn = wid >> 1;
    const int g = lane >> 2, t = lane & 3;
    const int m0 = blockIdx.y * 128, n0 = blockIdx.x * 128;

    // ---- loader setup ----
    const float* asrc[4]; unsigned asz[4]; uint32_t a_dst[4];
    uint32_t sA = smem_u32(&As[0][0][0]);
    uint32_t sB = smem_u32(&Bs[0][0][0]);
    #pragma unroll
    for (int j = 0; j < 4; j++) {
        int rl = j*32 + (tid >> 2);           // row within block tile
        int r = m0 + rl;
        bool v = r < M;
        int gr = 0;
        if (v) gr = GATHER ? gidx[r] : r;
        asrc[j] = A + (size_t)gr * K + (tid & 3) * 4;
        asz[j] = v ? 16u : 0u;
        a_dst[j] = sA + (uint32_t)(rl*20 + (tid & 3)*4) * 4;
    }
    const float* bsrc[4]; uint32_t b_dst[4];
    #pragma unroll
    for (int j = 0; j < 4; j++) {
        int kr = j*4 + (tid >> 5);
        int nc = (tid & 31) * 4;
        bsrc[j] = Bm + (size_t)kr * N + n0 + nc;
        b_dst[j] = sB + (uint32_t)(kr*136 + nc) * 4;
    }

    // ---- ldmatrix lane addressing (A) ----
    int a_row = wm*64 + (lane & 7) + ((lane >> 3) & 1) * 8;
    int a_kc  = ((lane >> 4) & 1) * 4;
    uint32_t a_ld = sA + (uint32_t)(a_row*20 + a_kc) * 4;

    // issue tile stage for k0
    #define ISSUE_TILE(stage, k0) do { \
        _Pragma("unroll") \
        for (int j = 0; j < 4; j++) \
            cpasync16(a_dst[j] + (stage)*ABYTES_, asrc[j] + (k0), asz[j]); \
        _Pragma("unroll") \
        for (int j = 0; j < 4; j++) \
            cpasync16(b_dst[j] + (stage)*BBYTES_, bsrc[j] + (size_t)(k0)*N, 16u); \
        cpcommit(); \
    } while (0)

    float acc[4][8][4] = {};
    int ntiles = K >> 4;

    ISSUE_TILE(0, 0);
    for (int it = 0; it < ntiles; it++) {
        int cur = it & 1;
        cpwait0();
        __syncthreads();
        if (it + 1 < ntiles) ISSUE_TILE(cur ^ 1, (it + 1) << 4);
        #pragma unroll
        for (int kk = 0; kk < 16; kk += 8) {
            uint32_t a[4][4];
            #pragma unroll
            for (int mt = 0; mt < 4; mt++)
                ldsm4(a[mt], a_ld + cur*ABYTES_ + mt*1280 + kk*4);
            uint32_t b[8][2];
            #pragma unroll
            for (int nt = 0; nt < 8; nt++) {
                int nb = wn*64 + nt*8 + g;
                b[nt][0] = __float_as_uint(Bs[cur][kk + t][nb]);
                b[nt][1] = __float_as_uint(Bs[cur][kk + t + 4][nb]);
            }
            #pragma unroll
            for (int mt = 0; mt < 4; mt++)
                #pragma unroll
                for (int nt = 0; nt < 8; nt++)
                    mma16n8k8(acc[mt][nt], a[mt], b[nt]);
        }
        __syncthreads();
    }
    #undef ISSUE_TILE

    // ---- epilogue ----
    #pragma unroll
    for (int mt = 0; mt < 4; mt++) {
        #pragma unroll
        for (int nt = 0; nt < 8; nt++) {
            int n = n0 + wn*64 + nt*8 + t*2;
            float bi0 = bias[n], bi1 = bias[n + 1];
            #pragma unroll
            for (int half = 0; half < 2; half++) {
                int m = m0 + wm*64 + mt*16 + g + half*8;
                if (m < M) {
                    float v0 = acc[mt][nt][half*2 + 0] + bi0;
                    float v1 = acc[mt][nt][half*2 + 1] + bi1;
                    if (ACT == 1) {
                        v0 = 0.5f * v0 * (1.f + erff(v0 * 0.70710678118654752f));
                        v1 = 0.5f * v1 * (1.f + erff(v1 * 0.70710678118654752f));
                    }
                    size_t off = (size_t)m * N + n;
                    if (RESID) { v0 += Rm[off]; v1 += Rm[off + 1]; }
                    if (ROUND_OUT) { v0 = tf32r(v0); v1 = tf32r(v1); }
                    float2 o; o.x = v0; o.y = v1;
                    *(float2*)&C[off] = o;
                }
            }
        }
    }
}

// ---------------- logits: Q @ K^T via mma (both operands LDSM) --------------
__global__ __launch_bounds__(128) void logits_tc() {
    int bh = blockIdx.z; int b = bh / H_, h = bh % H_;
    int i0 = blockIdx.y * 64, j0 = blockIdx.x * 64;
    __shared__ __align__(128) float Qs[64][68];   // i-major, 64 k + pad
    __shared__ __align__(128) float Ks[64][68];   // j-major, 64 k + pad
    const int tid = threadIdx.x, lane = tid & 31, wid = tid >> 5;
    const int wm = wid & 1, wn = wid >> 1;
    const int g = lane >> 2, t = lane & 3;

    #pragma unroll
    for (int q = 0; q < 8; q++) {
        int idx = q*128 + tid;
        int r = idx >> 4, c4 = (idx & 15) * 4;
        int i = i0 + r;
        float4 v = make_float4(0.f, 0.f, 0.f, 0.f);
        if (i < KS_) v = *(const float4*)&g_qsel[((size_t)(b*KS_ + i))*D_ + h*DH_ + c4];
        Qs[r][c4+0] = tf32r(v.x); Qs[r][c4+1] = tf32r(v.y);
        Qs[r][c4+2] = tf32r(v.z); Qs[r][c4+3] = tf32r(v.w);
        float4 w = *(const float4*)&g_kf[((size_t)(b*L_ + j0 + r))*D_ + h*DH_ + c4];
        Ks[r][c4+0] = tf32r(w.x); Ks[r][c4+1] = tf32r(w.y);
        Ks[r][c4+2] = tf32r(w.z); Ks[r][c4+3] = tf32r(w.w);
    }
    __syncthreads();

    uint32_t sQ = smem_u32(&Qs[0][0]);
    uint32_t sK = smem_u32(&Ks[0][0]);
    int a_row = wm*32 + (lane & 7) + ((lane >> 3) & 1) * 8;
    int a_kc  = ((lane >> 4) & 1) * 4;
    uint32_t a_ld = sQ + (uint32_t)(a_row*68 + a_kc) * 4;
    int b_row = wn*32 + (lane & 7) + ((lane >> 4) & 1) * 8;
    int b_kc  = ((lane >> 3) & 1) * 4;
    uint32_t b_ld = sK + (uint32_t)(b_row*68 + b_kc) * 4;

    float acc[2][4][4] = {};
    #pragma unroll
    for (int kk = 0; kk < 64; kk += 8) {
        uint32_t a[2][4], bb[2][4];
        #pragma unroll
        for (int mt = 0; mt < 2; mt++) ldsm4(a[mt], a_ld + mt*(16*68*4) + kk*4);
        #pragma unroll
        for (int nb = 0; nb < 2; nb++) ldsm4(bb[nb], b_ld + nb*(16*68*4) + kk*4);
        #pragma unroll
        for (int mt = 0; mt < 2; mt++)
            #pragma unroll
            for (int nt = 0; nt < 4; nt++) {
                uint32_t bf[2] = { bb[nt>>1][(nt&1)*2], bb[nt>>1][(nt&1)*2 + 1] };
                mma16n8k8(acc[mt][nt], a[mt], bf);
            }
    }

    const float scale = 0.125f;
    #pragma unroll
    for (int mt = 0; mt < 2; mt++) {
        #pragma unroll
        for (int nt = 0; nt < 4; nt++) {
            int j = j0 + wn*32 + nt*8 + t*2;
            #pragma unroll
            for (int half = 0; half < 2; half++) {
                int i = i0 + wm*32 + mt*16 + g + half*8;
                if (i < KS_) {
                    float* p = &g_logits[((size_t)bh*KS_ + i)*L_ + j];
                    p[0] = acc[mt][nt][half*2 + 0] * scale;
                    p[1] = acc[mt][nt][half*2 + 1] * scale;
                }
            }
        }
    }
}

// ---------------- softmax over keys ----------------
__global__ void softmax_kernel() {
    size_t row = blockIdx.x;
    float* p = g_logits + row * (size_t)L_;
    int t = threadIdx.x;   // 256
    __shared__ float sh[32];
    float v[8]; float mx = -1e30f;
    #pragma unroll
    for (int i = 0; i < 8; i++) { v[i] = p[t + 256*i]; mx = fmaxf(mx, v[i]); }
    mx = blockReduceMax(mx, sh);
    float s = 0.f;
    #pragma unroll
    for (int i = 0; i < 8; i++) { v[i] = expf(v[i] - mx); s += v[i]; }
    s = blockReduceSum(s, sh);
    float inv = 1.f / s;
    #pragma unroll
    for (int i = 0; i < 8; i++) p[t + 256*i] = v[i] * inv;
}

// ---------------- ctx = probs @ V via mma ----------------
__global__ __launch_bounds__(128) void ctx_tc() {
    int bh = blockIdx.y; int b = bh / H_, h = bh % H_;
    int i0 = blockIdx.x * 64;
    __shared__ __align__(128) float Ps[64][36];   // i-major, 32 k + pad
    __shared__ __align__(128) float Vs[32][72];   // k-major, 64 n + pad
    const int tid = threadIdx.x, lane = tid & 31, wid = tid >> 5;
    const int wm = wid & 1, wn = wid >> 1;
    const int g = lane >> 2, t = lane & 3;

    uint32_t sP = smem_u32(&Ps[0][0]);
    int a_row = wm*32 + (lane & 7) + ((lane >> 3) & 1) * 8;
    int a_kc  = ((lane >> 4) & 1) * 4;
    uint32_t a_ld = sP + (uint32_t)(a_row*36 + a_kc) * 4;

    float acc[2][4][4] = {};
    for (int l0 = 0; l0 < L_; l0 += 32) {
        #pragma unroll
        for (int q = 0; q < 4; q++) {
            int idx = q*128 + tid;
            int r = idx >> 3, c4 = (idx & 7) * 4;
            int i = i0 + r;
            float4 v = make_float4(0.f, 0.f, 0.f, 0.f);
            if (i < KS_) v = *(const float4*)&g_logits[((size_t)bh*KS_ + i)*L_ + l0 + c4];
            Ps[r][c4+0] = tf32r(v.x); Ps[r][c4+1] = tf32r(v.y);
            Ps[r][c4+2] = tf32r(v.z); Ps[r][c4+3] = tf32r(v.w);
        }
        #pragma unroll
        for (int q = 0; q < 4; q++) {
            int idx = q*128 + tid;
            int r = idx >> 4, c4 = (idx & 15) * 4;
            float4 w = *(const float4*)&g_vf[((size_t)(b*L_ + l0 + r))*D_ + h*DH_ + c4];
            Vs[r][c4+0] = tf32r(w.x); Vs[r][c4+1] = tf32r(w.y);
            Vs[r][c4+2] = tf32r(w.z); Vs[r][c4+3] = tf32r(w.w);
        }
        __syncthreads();
        #pragma unroll
        for (int kk = 0; kk < 32; kk += 8) {
            uint32_t a[2][4];
            #pragma unroll
            for (int mt = 0; mt < 2; mt++) ldsm4(a[mt], a_ld + mt*(16*36*4) + kk*4);
            uint32_t bv[4][2];
            #pragma unroll
            for (int nt = 0; nt < 4; nt++) {
                int nb = wn*32 + nt*8 + g;
                bv[nt][0] = __float_as_uint(Vs[kk + t][nb]);
                bv[nt][1] = __float_as_uint(Vs[kk + t + 4][nb]);
            }
            #pragma unroll
            for (int mt = 0; mt < 2; mt++)
                #pragma unroll
                for (int nt = 0; nt < 4; nt++)
                    mma16n8k8(acc[mt][nt], a[mt], bv[nt]);
        }
        __syncthreads();
    }

    #pragma unroll
    for (int mt = 0; mt < 2; mt++) {
        #pragma unroll
        for (int nt = 0; nt < 4; nt++) {
            int n = wn*32 + nt*8 + t*2;
            #pragma unroll
            for (int half = 0; half < 2; half++) {
                int i = i0 + wm*32 + mt*16 + g + half*8;
                if (i < KS_) {
                    float* p = &g_ctx[((size_t)(b*KS_ + i))*D_ + h*DH_ + n];
                    // round: feeds Wo GEMM (cp.async path)
                    p[0] = tf32r(acc[mt][nt][half*2 + 0]);
                    p[1] = tf32r(acc[mt][nt][half*2 + 1]);
                }
            }
        }
    }
}

// ---------------- merge paths + residual + LN2 ----------------
__global__ void merge_ln2_kernel(const float* __restrict__ x, const float* __restrict__ g2,
                                 const float* __restrict__ b2) {
    int tok = blockIdx.x;
    int b = tok >> 11;
    int t = threadIdx.x;
    int pos = g_selpos[tok];
    float sc = g_scores[tok];
    __shared__ float sh[32];
    float hv[3]; float s = 0.f, sq = 0.f;
    #pragma unroll
    for (int i = 0; i < 3; i++) {
        int d = t + 256*i;
        float mg;
        if (pos >= 0) mg = g_attno[(size_t)pos*D_ + d];
        else          mg = g_mixb[(size_t)tok*D_ + d] + sc * g_pooledWm[b*D_ + d];
        float u = x[(size_t)tok*D_ + d] + mg;
        hv[i] = u;
        g_h[(size_t)tok*D_ + d] = u;
        s += u; sq += u*u;
    }
    s  = blockReduceSum(s,  sh);
    sq = blockReduceSum(sq, sh);
    float mean = s * (1.f/D_);
    float rstd = rsqrtf(sq*(1.f/D_) - mean*mean + 1e-5f);
    #pragma unroll
    for (int i = 0; i < 3; i++) {
        int d = t + 256*i;
        // rounded: n2 only feeds FFN1 GEMM (cp.async path)
        g_n2[(size_t)tok*D_ + d] = tf32r((hv[i] - mean) * rstd * g2[d] + b2[d]);
    }
}

// ---------------- host launch ----------------
extern "C" void kernel_launch(void* const* d_in, const int* in_sizes, int n_in,
                              void* d_out, int out_size) {
    (void)in_sizes; (void)n_in; (void)out_size;
    const float* x   = (const float*)d_in[0];
    const float* g1  = (const float*)d_in[1];
    const float* b1  = (const float*)d_in[2];
    const float* g2  = (const float*)d_in[3];
    const float* b2  = (const float*)d_in[4];
    const float* Wr  = (const float*)d_in[5];
    const float* br  = (const float*)d_in[6];
    const float* Wq  = (const float*)d_in[7];
    const float* bq  = (const float*)d_in[8];
    const float* Wk  = (const float*)d_in[9];
    const float* bk  = (const float*)d_in[10];
    const float* Wv  = (const float*)d_in[11];
    const float* bv  = (const float*)d_in[12];
    const float* Wo  = (const float*)d_in[13];
    const float* bo  = (const float*)d_in[14];
    const float* Wm  = (const float*)d_in[15];
    const float* bm  = (const float*)d_in[16];
    const float* W1  = (const float*)d_in[17];
    const float* bf1 = (const float*)d_in[18];
    const float* W2  = (const float*)d_in[19];
    const float* bf2 = (const float*)d_in[20];
    float* out = (float*)d_out;

    float *p_normedr, *p_kf, *p_vf, *p_mixb, *p_qsel, *p_ctx, *p_attno, *p_h, *p_n2, *p_t;
    float *p_wbuf;
    int* p_selidx;
    cudaGetSymbolAddress((void**)&p_normedr, g_normedr);
    cudaGetSymbolAddress((void**)&p_kf,     g_kf);
    cudaGetSymbolAddress((void**)&p_vf,     g_vf);
    cudaGetSymbolAddress((void**)&p_mixb,   g_mixb);
    cudaGetSymbolAddress((void**)&p_qsel,   g_qsel);
    cudaGetSymbolAddress((void**)&p_ctx,    g_ctx);
    cudaGetSymbolAddress((void**)&p_attno,  g_attno);
    cudaGetSymbolAddress((void**)&p_h,      g_h);
    cudaGetSymbolAddress((void**)&p_n2,     g_n2);
    cudaGetSymbolAddress((void**)&p_t,      g_t);
    cudaGetSymbolAddress((void**)&p_wbuf,   g_wbuf);
    cudaGetSymbolAddress((void**)&p_selidx, g_selidx);

    float* rWq = p_wbuf + 0*(size_t)WSZ_;
    float* rWk = p_wbuf + 1*(size_t)WSZ_;
    float* rWv = p_wbuf + 2*(size_t)WSZ_;
    float* rWo = p_wbuf + 3*(size_t)WSZ_;
    float* rWm = p_wbuf + 4*(size_t)WSZ_;
    float* rW1 = p_wbuf + 5*(size_t)WSZ_;
    float* rW2 = rW1 + (size_t)W1SZ_;

    // 0. round weights to tf32
    round_w_kernel<<<512, 256>>>(Wq, rWq, WSZ_/4);
    round_w_kernel<<<512, 256>>>(Wk, rWk, WSZ_/4);
    round_w_kernel<<<512, 256>>>(Wv, rWv, WSZ_/4);
    round_w_kernel<<<512, 256>>>(Wo, rWo, WSZ_/4);
    round_w_kernel<<<512, 256>>>(Wm, rWm, WSZ_/4);
    round_w_kernel<<<512, 256>>>(W1, rW1, W1SZ_/4);
    round_w_kernel<<<512, 256>>>(W2, rW2, W1SZ_/4);
    // 1. LN1 + router
    ln1_router_kernel<<<BL_, 256>>>(x, g1, b1, Wr, br);
    // 2. top-k
    topk_kernel<<<B_, 1024>>>();
    // 3. pooling path (exact fp32)
    pooled_part_kernel<<<dim3(16, B_), D_>>>();
    pooled_fin_kernel<<<B_, D_>>>();
    pooledwm_kernel<<<dim3(3, B_), 256>>>(Wm);
    // 4. dense projections K, V, mixbase
    gemm_tc<0,false,false,false><<<dim3(D_/128, BL_/128), 128>>>(p_normedr, nullptr, rWk, bk, nullptr, p_kf,   BL_,  D_, D_);
    gemm_tc<0,false,false,false><<<dim3(D_/128, BL_/128), 128>>>(p_normedr, nullptr, rWv, bv, nullptr, p_vf,   BL_,  D_, D_);
    gemm_tc<0,false,false,false><<<dim3(D_/128, BL_/128), 128>>>(p_normedr, nullptr, rWm, bm, nullptr, p_mixb, BL_,  D_, D_);
    // 5. Q for selected rows
    gemm_tc<0,true ,false,false><<<dim3(D_/128, (MSEL_+127)/128), 128>>>(p_normedr, p_selidx, rWq, bq, nullptr, p_qsel, MSEL_, D_, D_);
    // 6. attention
    logits_tc<<<dim3(L_/64, (KS_+63)/64, B_*H_), 128>>>();
    softmax_kernel<<<B_*H_*KS_, 256>>>();
    ctx_tc<<<dim3((KS_+63)/64, B_*H_), 128>>>();
    gemm_tc<0,false,false,false><<<dim3(D_/128, (MSEL_+127)/128), 128>>>(p_ctx, nullptr, rWo, bo, nullptr, p_attno, MSEL_, D_, D_);
    // 7. merge + residual + LN2
    merge_ln2_kernel<<<BL_, 256>>>(x, g2, b2);
    // 8. FFN
    gemm_tc<1,false,false,true ><<<dim3(F_/128, BL_/128), 128>>>(p_n2, nullptr, rW1, bf1, nullptr, p_t, BL_, F_, D_);
    gemm_tc<0,false,true ,false><<<dim3(D_/128, BL_/128), 128>>>(p_t,  nullptr, rW2, bf2, p_h,    out, BL_, D_, F_);
}